// round 2
// baseline (speedup 1.0000x reference)
#include <cuda_runtime.h>
#include <math.h>

#define NN 500000
#define FF 128
#define HH 64
#define BB 1024
#define TN 64

// scratch (no allocations allowed)
__device__ float g_e[2][NN];
__device__ float g_esort[2][NN];
__device__ int   g_idx[2][NN];
__device__ int   g_count[2][BB];
__device__ int   g_offset[2][BB + 1];
__device__ int   g_cursor[2][BB];

// ---------------- K0: init ----------------
__global__ void init_kernel(float* __restrict__ out) {
    int i = blockIdx.x * blockDim.x + threadIdx.x;
    if (i < BB * FF) out[i] = 0.0f;
    if (i < 2 * BB) (&g_count[0][0])[i] = 0;
}

// ---------------- K1: fused score MLP ----------------
// CTA: 256 threads, 64-node tile. smem: xs[128][68] (transposed x tile),
// ws[128][64] (W1), red[64][17] (h->score reduction).
#define XS_STRIDE 68
#define SMEM_F (FF * XS_STRIDE + FF * HH + TN * 17)

__global__ __launch_bounds__(256) void score_kernel(
    const float* __restrict__ x1, const float* __restrict__ x2,
    const int* __restrict__ bA, const int* __restrict__ bB,
    const float* __restrict__ W1, const float* __restrict__ b1v,
    const float* __restrict__ W2)
{
    extern __shared__ float sm[];
    float* xs  = sm;                       // [128][68]
    float* ws  = sm + FF * XS_STRIDE;      // [128][64]
    float* red = ws + FF * HH;             // [64][17]

    const int t   = blockIdx.y;
    const float* x = t ? x2 : x1;
    const int* batch = t ? bB : bA;
    const int n0  = blockIdx.x * TN;
    const int tid = threadIdx.x;

    // stage W1 -> ws[k][j]  (8192 floats = 2048 float4)
    #pragma unroll
    for (int m = 0; m < 8; ++m) {
        int idx4 = tid + 256 * m;
        ((float4*)ws)[idx4] = ((const float4*)W1)[idx4];
    }

    // stage x tile transposed: xs[k][n]
    {
        int n  = tid & 63;
        int c0 = tid >> 6;          // 0..3
        int g  = n0 + n;
        #pragma unroll
        for (int m = 0; m < 8; ++m) {
            int c4 = c0 + 4 * m;    // 0..31 (float4 index within row)
            float4 v = make_float4(0.f, 0.f, 0.f, 0.f);
            if (g < NN) v = ((const float4*)x)[g * 32 + c4];
            int k = 4 * c4;
            xs[(k + 0) * XS_STRIDE + n] = v.x;
            xs[(k + 1) * XS_STRIDE + n] = v.y;
            xs[(k + 2) * XS_STRIDE + n] = v.z;
            xs[(k + 3) * XS_STRIDE + n] = v.w;
        }
    }
    __syncthreads();

    const int i = tid & 15;   // node group: nodes 4i..4i+3
    const int j = tid >> 4;   // hidden group: h 4j..4j+3

    float acc[4][4];
    #pragma unroll
    for (int a = 0; a < 4; ++a)
        #pragma unroll
        for (int b = 0; b < 4; ++b) acc[a][b] = 0.0f;

    #pragma unroll 8
    for (int k = 0; k < FF; ++k) {
        float4 xv = *(const float4*)&xs[k * XS_STRIDE + 4 * i];
        float4 wv = *(const float4*)&ws[k * HH + 4 * j];
        float xr[4] = {xv.x, xv.y, xv.z, xv.w};
        float wr[4] = {wv.x, wv.y, wv.z, wv.w};
        #pragma unroll
        for (int a = 0; a < 4; ++a)
            #pragma unroll
            for (int b = 0; b < 4; ++b)
                acc[a][b] = fmaf(xr[a], wr[b], acc[a][b]);
    }

    // epilogue: tanh + W2 dot (b2 cancels in softmax, omitted)
    float4 bb = ((const float4*)b1v)[j];
    float4 w2 = ((const float4*)W2)[j];
    #pragma unroll
    for (int a = 0; a < 4; ++a) {
        float p = tanhf(acc[a][0] + bb.x) * w2.x
                + tanhf(acc[a][1] + bb.y) * w2.y
                + tanhf(acc[a][2] + bb.z) * w2.z
                + tanhf(acc[a][3] + bb.w) * w2.w;
        red[(4 * i + a) * 17 + j] = p;
    }
    __syncthreads();

    if (tid < TN) {
        float s = 0.0f;
        #pragma unroll
        for (int jj = 0; jj < 16; ++jj) s += red[tid * 17 + jj];
        int g = n0 + tid;
        if (g < NN) {
            g_e[t][g] = expf(s);
            atomicAdd(&g_count[t][batch[g]], 1);
        }
    }
}

// ---------------- K2: exclusive prefix scan over segments ----------------
__global__ void scan_kernel() {
    __shared__ int ss[BB];
    int tid = threadIdx.x;
    for (int t = 0; t < 2; ++t) {
        int v = g_count[t][tid];
        ss[tid] = v;
        __syncthreads();
        for (int d = 1; d < BB; d <<= 1) {
            int add = (tid >= d) ? ss[tid - d] : 0;
            __syncthreads();
            ss[tid] += add;
            __syncthreads();
        }
        int incl = ss[tid];
        g_offset[t][tid] = incl - v;
        g_cursor[t][tid] = incl - v;
        if (tid == BB - 1) g_offset[t][BB] = incl;
        __syncthreads();
    }
}

// ---------------- K3: scatter nodes into segment-sorted order ----------------
__global__ void scatter_kernel(const int* __restrict__ bA, const int* __restrict__ bB) {
    int t = blockIdx.y;
    int i = blockIdx.x * blockDim.x + threadIdx.x;
    if (i >= NN) return;
    const int* batch = t ? bB : bA;
    int b = batch[i];
    int p = atomicAdd(&g_cursor[t][b], 1);
    g_idx[t][p]   = i;
    g_esort[t][p] = g_e[t][i];
}

// ---------------- K4: per-segment weighted pooling ----------------
__global__ __launch_bounds__(256) void pool_kernel(
    const float* __restrict__ x1, const float* __restrict__ x2,
    float* __restrict__ out)
{
    const int t = blockIdx.y;
    const int b = blockIdx.x;
    const float* x = t ? x2 : x1;
    const int start = g_offset[t][b];
    const int end   = g_offset[t][b + 1];
    const int f    = threadIdx.x & 127;
    const int slot = threadIdx.x >> 7;

    float acc = 0.0f, es = 0.0f;
    #pragma unroll 4
    for (int p = start + slot; p < end; p += 2) {
        int   n = g_idx[t][p];
        float e = g_esort[t][p];
        acc = fmaf(e, x[n * FF + f], acc);
        es += e;
    }

    __shared__ float sa[128];
    __shared__ float se[2];
    if (slot == 1) { sa[f] = acc; if (f == 0) se[1] = es; }
    else if (f == 0) se[0] = es;
    __syncthreads();

    if (slot == 0 && end > start) {
        float tot = acc + sa[f];
        float s   = se[0] + se[1];
        atomicAdd(&out[b * FF + f], 0.5f * tot / s);
    }
}

// ---------------- launch ----------------
extern "C" void kernel_launch(void* const* d_in, const int* in_sizes, int n_in,
                              void* d_out, int out_size) {
    const float *x1 = 0, *x2 = 0, *W1 = 0, *b1v = 0, *W2 = 0;
    const int *bt1 = 0, *bt2 = 0;
    for (int k = 0; k < n_in; ++k) {
        long s = in_sizes[k];
        if (s == (long)NN * FF) { if (!x1) x1 = (const float*)d_in[k]; else if (!x2) x2 = (const float*)d_in[k]; }
        else if (s == NN)       { if (!bt1) bt1 = (const int*)d_in[k]; else if (!bt2) bt2 = (const int*)d_in[k]; }
        else if (s == FF * HH)  { W1 = (const float*)d_in[k]; }
        else if (s == HH)       { if (!b1v) b1v = (const float*)d_in[k]; else if (!W2) W2 = (const float*)d_in[k]; }
        // size-1 entries (B scalar, b2): b2 is a constant shift -> cancels in softmax; ignored.
    }
    float* out = (float*)d_out;

    init_kernel<<<(BB * FF + 255) / 256, 256>>>(out);

    const int smem_bytes = SMEM_F * (int)sizeof(float);
    cudaFuncSetAttribute(score_kernel, cudaFuncAttributeMaxDynamicSharedMemorySize, smem_bytes);
    dim3 g1((NN + TN - 1) / TN, 2);
    score_kernel<<<g1, 256, smem_bytes>>>(x1, x2, bt1, bt2, W1, b1v, W2);

    scan_kernel<<<1, BB>>>();

    dim3 g3((NN + 255) / 256, 2);
    scatter_kernel<<<g3, 256>>>(bt1, bt2);

    dim3 g4(BB, 2);
    pool_kernel<<<g4, 256>>>(x1, x2, out);
}

// round 4
// speedup vs baseline: 1.4027x; 1.4027x over previous
#include <cuda_runtime.h>
#include <math.h>
#include <stdint.h>

#define NN 500000
#define FF 128
#define HH 64
#define BB 1024
#define TILE 128
#define XS_STRIDE 132
#define WS_STRIDE 72

// ---------------- scratch (no allocations allowed) ----------------
__device__ float g_e[2][NN];
__device__ float g_esort[2][NN];
__device__ int   g_idx[2][NN];
__device__ int   g_count[2][BB];
__device__ int   g_offset[2][BB + 1];
__device__ int   g_cursor[2][BB];

// ---------------- helpers ----------------
__device__ __forceinline__ uint32_t tf32_rna_u(float x) {
    uint32_t u; asm("cvt.rna.tf32.f32 %0, %1;" : "=r"(u) : "f"(x));
    return u;
}
__device__ __forceinline__ float tanh_fast(float v) {
    float e = __expf(2.0f * v);
    return 1.0f - __fdividef(2.0f, e + 1.0f);
}
// D += A(tf32) * B(tf32), m16n8k8, A row-major, B col-major (B[k][n])
__device__ __forceinline__ void mma_tf32(float* c, const uint32_t* a, const uint32_t* b) {
    asm volatile(
        "mma.sync.aligned.m16n8k8.row.col.f32.tf32.tf32.f32 "
        "{%0,%1,%2,%3}, {%4,%5,%6,%7}, {%8,%9}, {%0,%1,%2,%3};"
        : "+f"(c[0]), "+f"(c[1]), "+f"(c[2]), "+f"(c[3])
        : "r"(a[0]), "r"(a[1]), "r"(a[2]), "r"(a[3]), "r"(b[0]), "r"(b[1]));
}

// ---------------- K0: init ----------------
__global__ void init_kernel(float* __restrict__ out) {
    int i = blockIdx.x * blockDim.x + threadIdx.x;
    if (i < BB * FF) out[i] = 0.0f;
    if (i < 2 * BB) (&g_count[0][0])[i] = 0;
}

// ---------------- K1: mma.sync tf32x3 score kernel ----------------
// smem: xs[128][132] raw x tile, ws[128][72] raw W1, b1s[64], w2s[64]
#define SMEM_F (TILE * XS_STRIDE + FF * WS_STRIDE + 64 + 64)

__global__ __launch_bounds__(128) void score_mma_kernel(
    const float* __restrict__ x1, const float* __restrict__ x2,
    const int* __restrict__ bA, const int* __restrict__ bB,
    const float* __restrict__ W1, const float* __restrict__ b1v,
    const float* __restrict__ W2)
{
    extern __shared__ float sm[];
    float* xs  = sm;
    float* ws  = xs + TILE * XS_STRIDE;
    float* b1s = ws + FF * WS_STRIDE;
    float* w2s = b1s + 64;

    const int tid  = threadIdx.x;
    const int wid  = tid >> 5;
    const int lane = tid & 31;
    const int g    = lane >> 2;   // 0..7
    const int tq   = lane & 3;    // 0..3
    const int t    = blockIdx.y;
    const float* x = t ? x2 : x1;
    const int* batch = t ? bB : bA;
    const int n0   = blockIdx.x * TILE;

    // stage W1 [128 x 64] into ws[k][n] stride 72
    const float4* W14 = (const float4*)W1;
    #pragma unroll
    for (int m = 0; m < 16; ++m) {
        int j = tid + 128 * m;          // float4 id 0..2047
        float4 v = W14[j];
        int k = j >> 4;                 // 16 float4 per k-row
        int c = (j & 15) * 4;
        *(float4*)&ws[k * WS_STRIDE + c] = v;
    }
    if (tid < HH) { b1s[tid] = b1v[tid]; w2s[tid] = W2[tid]; }

    // stage x tile [128 nodes x 128 f] into xs[r][k] stride 132
    #pragma unroll
    for (int m = 0; m < 32; ++m) {
        int idx = m * 128 + tid;        // float4 id within tile
        int r = idx >> 5;
        int q = idx & 31;
        int node = n0 + r;
        float4 v = make_float4(0.f, 0.f, 0.f, 0.f);
        if (node < NN) v = ((const float4*)x)[node * 32 + q];
        *(float4*)&xs[r * XS_STRIDE + q * 4] = v;
    }
    __syncthreads();

    const int base = wid * 32;
    float acc[2][8][4];
    #pragma unroll
    for (int m = 0; m < 2; ++m)
        #pragma unroll
        for (int n = 0; n < 8; ++n)
            #pragma unroll
            for (int c = 0; c < 4; ++c) acc[m][n][c] = 0.0f;

    #pragma unroll
    for (int kt = 0; kt < 16; ++kt) {
        const int k0 = kt * 8;

        // B fragments for all 8 n-tiles (hi + lo)
        uint32_t bh[8][2], bl[8][2];
        #pragma unroll
        for (int n = 0; n < 8; ++n) {
            float r0 = ws[(k0 + tq)     * WS_STRIDE + n * 8 + g];
            float r1 = ws[(k0 + 4 + tq) * WS_STRIDE + n * 8 + g];
            uint32_t h0 = tf32_rna_u(r0);
            uint32_t h1 = tf32_rna_u(r1);
            bh[n][0] = h0; bh[n][1] = h1;
            bl[n][0] = tf32_rna_u(r0 - __uint_as_float(h0));
            bl[n][1] = tf32_rna_u(r1 - __uint_as_float(h1));
        }

        #pragma unroll
        for (int m = 0; m < 2; ++m) {
            const int r = base + m * 16 + g;
            float a0 = xs[r       * XS_STRIDE + k0 + tq];
            float a1 = xs[(r + 8) * XS_STRIDE + k0 + tq];
            float a2 = xs[r       * XS_STRIDE + k0 + 4 + tq];
            float a3 = xs[(r + 8) * XS_STRIDE + k0 + 4 + tq];
            uint32_t ahi[4], alo[4];
            ahi[0] = tf32_rna_u(a0); alo[0] = tf32_rna_u(a0 - __uint_as_float(ahi[0]));
            ahi[1] = tf32_rna_u(a1); alo[1] = tf32_rna_u(a1 - __uint_as_float(ahi[1]));
            ahi[2] = tf32_rna_u(a2); alo[2] = tf32_rna_u(a2 - __uint_as_float(ahi[2]));
            ahi[3] = tf32_rna_u(a3); alo[3] = tf32_rna_u(a3 - __uint_as_float(ahi[3]));

            #pragma unroll
            for (int n = 0; n < 8; ++n) {
                mma_tf32(acc[m][n], ahi, bh[n]);
                mma_tf32(acc[m][n], ahi, bl[n]);
                mma_tf32(acc[m][n], alo, bh[n]);
            }
        }
    }

    // epilogue: tanh + W2 dot, butterfly over the 4 lanes holding each row
    #pragma unroll
    for (int m = 0; m < 2; ++m) {
        #pragma unroll
        for (int half = 0; half < 2; ++half) {
            float s = 0.0f;
            #pragma unroll
            for (int n = 0; n < 8; ++n) {
                #pragma unroll
                for (int c = 0; c < 2; ++c) {
                    int col = n * 8 + 2 * tq + c;
                    float h = acc[m][n][half * 2 + c] + b1s[col];
                    s = fmaf(tanh_fast(h), w2s[col], s);
                }
            }
            s += __shfl_xor_sync(0xffffffffu, s, 1);
            s += __shfl_xor_sync(0xffffffffu, s, 2);
            if (tq == 0) {
                int node = n0 + base + m * 16 + half * 8 + g;
                if (node < NN) {
                    g_e[t][node] = __expf(s);
                    atomicAdd(&g_count[t][batch[node]], 1);
                }
            }
        }
    }
}

// ---------------- K2: exclusive prefix scan over segments ----------------
__global__ void scan_kernel() {
    __shared__ int ss[BB];
    int tid = threadIdx.x;
    for (int t = 0; t < 2; ++t) {
        int v = g_count[t][tid];
        ss[tid] = v;
        __syncthreads();
        for (int d = 1; d < BB; d <<= 1) {
            int add = (tid >= d) ? ss[tid - d] : 0;
            __syncthreads();
            ss[tid] += add;
            __syncthreads();
        }
        int incl = ss[tid];
        g_offset[t][tid] = incl - v;
        g_cursor[t][tid] = incl - v;
        if (tid == BB - 1) g_offset[t][BB] = incl;
        __syncthreads();
    }
}

// ---------------- K3: scatter nodes into segment-sorted order (x4 ILP) ----------------
__global__ void scatter_kernel(const int* __restrict__ bA, const int* __restrict__ bB) {
    int t = blockIdx.y;
    int i0 = (blockIdx.x * blockDim.x + threadIdx.x) * 4;
    const int* batch = t ? bB : bA;
    int  b[4]; float e[4]; int p[4];
    #pragma unroll
    for (int u = 0; u < 4; ++u) {
        int i = i0 + u;
        if (i < NN) { b[u] = batch[i]; e[u] = g_e[t][i]; }
    }
    #pragma unroll
    for (int u = 0; u < 4; ++u) {
        int i = i0 + u;
        if (i < NN) p[u] = atomicAdd(&g_cursor[t][b[u]], 1);
    }
    #pragma unroll
    for (int u = 0; u < 4; ++u) {
        int i = i0 + u;
        if (i < NN) { g_idx[t][p[u]] = i; g_esort[t][p[u]] = e[u]; }
    }
}

// ---------------- K4: per-segment weighted pooling ----------------
__global__ __launch_bounds__(256) void pool_kernel(
    const float* __restrict__ x1, const float* __restrict__ x2,
    float* __restrict__ out)
{
    const int t = blockIdx.y;
    const int b = blockIdx.x;
    const float* x = t ? x2 : x1;
    const int start = g_offset[t][b];
    const int end   = g_offset[t][b + 1];
    const int f    = threadIdx.x & 127;
    const int slot = threadIdx.x >> 7;

    float acc = 0.0f, es = 0.0f;
    #pragma unroll 4
    for (int p = start + slot; p < end; p += 2) {
        int   n = g_idx[t][p];
        float e = g_esort[t][p];
        acc = fmaf(e, x[n * FF + f], acc);
        es += e;
    }

    __shared__ float sa[128];
    __shared__ float se[2];
    if (slot == 1) { sa[f] = acc; if (f == 0) se[1] = es; }
    else if (f == 0) se[0] = es;
    __syncthreads();

    if (slot == 0 && end > start) {
        float tot = acc + sa[f];
        float s   = se[0] + se[1];
        atomicAdd(&out[b * FF + f], 0.5f * tot / s);
    }
}

// ---------------- launch ----------------
extern "C" void kernel_launch(void* const* d_in, const int* in_sizes, int n_in,
                              void* d_out, int out_size) {
    const float *x1 = 0, *x2 = 0, *W1 = 0, *b1v = 0, *W2 = 0;
    const int *bt1 = 0, *bt2 = 0;
    for (int k = 0; k < n_in; ++k) {
        long s = in_sizes[k];
        if (s == (long)NN * FF) { if (!x1) x1 = (const float*)d_in[k]; else if (!x2) x2 = (const float*)d_in[k]; }
        else if (s == NN)       { if (!bt1) bt1 = (const int*)d_in[k]; else if (!bt2) bt2 = (const int*)d_in[k]; }
        else if (s == FF * HH)  { W1 = (const float*)d_in[k]; }
        else if (s == HH)       { if (!b1v) b1v = (const float*)d_in[k]; else if (!W2) W2 = (const float*)d_in[k]; }
    }
    float* out = (float*)d_out;

    init_kernel<<<(BB * FF + 255) / 256, 256>>>(out);

    const int smem_bytes = SMEM_F * (int)sizeof(float);
    cudaFuncSetAttribute(score_mma_kernel, cudaFuncAttributeMaxDynamicSharedMemorySize, smem_bytes);
    dim3 g1((NN + TILE - 1) / TILE, 2);
    score_mma_kernel<<<g1, 128, smem_bytes>>>(x1, x2, bt1, bt2, W1, b1v, W2);

    scan_kernel<<<1, BB>>>();

    dim3 g3((NN / 4 + 255) / 256, 2);
    scatter_kernel<<<g3, 256>>>(bt1, bt2);

    dim3 g4(BB, 2);
    pool_kernel<<<g4, 256>>>(x1, x2, out);
}

// round 5
// speedup vs baseline: 1.4083x; 1.0039x over previous
#include <cuda_runtime.h>
#include <math.h>
#include <stdint.h>

#define NN 500000
#define FF 128
#define HH 64
#define BB 1024
#define TILE 128
#define XS_STRIDE 132
#define WS_STRIDE 72

// ---------------- scratch (no allocations allowed) ----------------
__device__ float g_e[2][NN];
__device__ float g_esort[2][NN];
__device__ int   g_idx[2][NN];
__device__ int   g_count[2][BB];
__device__ int   g_offset[2][BB + 1];
__device__ int   g_cursor[2][BB];

// ---------------- helpers ----------------
__device__ __forceinline__ uint32_t tf32_rna_u(float x) {
    uint32_t u; asm("cvt.rna.tf32.f32 %0, %1;" : "=r"(u) : "f"(x));
    return u;
}
__device__ __forceinline__ float tanh_fast(float v) {
    float e = __expf(2.0f * v);
    return 1.0f - __fdividef(2.0f, e + 1.0f);
}
// D += A(tf32) * B(tf32), m16n8k8, A row-major, B col-major (B[k][n])
__device__ __forceinline__ void mma_tf32(float* c, const uint32_t* a, const uint32_t* b) {
    asm volatile(
        "mma.sync.aligned.m16n8k8.row.col.f32.tf32.tf32.f32 "
        "{%0,%1,%2,%3}, {%4,%5,%6,%7}, {%8,%9}, {%0,%1,%2,%3};"
        : "+f"(c[0]), "+f"(c[1]), "+f"(c[2]), "+f"(c[3])
        : "r"(a[0]), "r"(a[1]), "r"(a[2]), "r"(a[3]), "r"(b[0]), "r"(b[1]));
}

// ---------------- K0: init ----------------
__global__ void init_kernel(float* __restrict__ out) {
    int i = blockIdx.x * blockDim.x + threadIdx.x;
    if (i < BB * FF) out[i] = 0.0f;
    if (i < 2 * BB) (&g_count[0][0])[i] = 0;
}

// ---------------- K1: mma.sync tf32x3 score kernel ----------------
// smem: xs[128][132] raw x tile, ws[128][72] raw W1, b1s[64], w2s[64]
#define SMEM_F (TILE * XS_STRIDE + FF * WS_STRIDE + 64 + 64)

__global__ __launch_bounds__(128) void score_mma_kernel(
    const float* __restrict__ x1, const float* __restrict__ x2,
    const int* __restrict__ bA, const int* __restrict__ bB,
    const float* __restrict__ W1, const float* __restrict__ b1v,
    const float* __restrict__ W2)
{
    extern __shared__ float sm[];
    float* xs  = sm;
    float* ws  = xs + TILE * XS_STRIDE;
    float* b1s = ws + FF * WS_STRIDE;
    float* w2s = b1s + 64;

    const int tid  = threadIdx.x;
    const int wid  = tid >> 5;
    const int lane = tid & 31;
    const int g    = lane >> 2;   // 0..7
    const int tq   = lane & 3;    // 0..3
    const int t    = blockIdx.y;
    const float* x = t ? x2 : x1;
    const int* batch = t ? bB : bA;
    const int n0   = blockIdx.x * TILE;

    // stage W1 [128 x 64] into ws[k][n] stride 72
    const float4* W14 = (const float4*)W1;
    #pragma unroll
    for (int m = 0; m < 16; ++m) {
        int j = tid + 128 * m;          // float4 id 0..2047
        float4 v = W14[j];
        int k = j >> 4;                 // 16 float4 per k-row
        int c = (j & 15) * 4;
        *(float4*)&ws[k * WS_STRIDE + c] = v;
    }
    if (tid < HH) { b1s[tid] = b1v[tid]; w2s[tid] = W2[tid]; }

    // stage x tile [128 nodes x 128 f] into xs[r][k] stride 132
    #pragma unroll
    for (int m = 0; m < 32; ++m) {
        int idx = m * 128 + tid;        // float4 id within tile
        int r = idx >> 5;
        int q = idx & 31;
        int node = n0 + r;
        float4 v = make_float4(0.f, 0.f, 0.f, 0.f);
        if (node < NN) v = ((const float4*)x)[node * 32 + q];
        *(float4*)&xs[r * XS_STRIDE + q * 4] = v;
    }
    __syncthreads();

    const int base = wid * 32;
    float acc[2][8][4];
    #pragma unroll
    for (int m = 0; m < 2; ++m)
        #pragma unroll
        for (int n = 0; n < 8; ++n)
            #pragma unroll
            for (int c = 0; c < 4; ++c) acc[m][n][c] = 0.0f;

    #pragma unroll
    for (int kt = 0; kt < 16; ++kt) {
        const int k0 = kt * 8;

        // B fragments for all 8 n-tiles (hi + lo)
        uint32_t bh[8][2], bl[8][2];
        #pragma unroll
        for (int n = 0; n < 8; ++n) {
            float r0 = ws[(k0 + tq)     * WS_STRIDE + n * 8 + g];
            float r1 = ws[(k0 + 4 + tq) * WS_STRIDE + n * 8 + g];
            uint32_t h0 = tf32_rna_u(r0);
            uint32_t h1 = tf32_rna_u(r1);
            bh[n][0] = h0; bh[n][1] = h1;
            bl[n][0] = tf32_rna_u(r0 - __uint_as_float(h0));
            bl[n][1] = tf32_rna_u(r1 - __uint_as_float(h1));
        }

        #pragma unroll
        for (int m = 0; m < 2; ++m) {
            const int r = base + m * 16 + g;
            float a0 = xs[r       * XS_STRIDE + k0 + tq];
            float a1 = xs[(r + 8) * XS_STRIDE + k0 + tq];
            float a2 = xs[r       * XS_STRIDE + k0 + 4 + tq];
            float a3 = xs[(r + 8) * XS_STRIDE + k0 + 4 + tq];
            uint32_t ahi[4], alo[4];
            ahi[0] = tf32_rna_u(a0); alo[0] = tf32_rna_u(a0 - __uint_as_float(ahi[0]));
            ahi[1] = tf32_rna_u(a1); alo[1] = tf32_rna_u(a1 - __uint_as_float(ahi[1]));
            ahi[2] = tf32_rna_u(a2); alo[2] = tf32_rna_u(a2 - __uint_as_float(ahi[2]));
            ahi[3] = tf32_rna_u(a3); alo[3] = tf32_rna_u(a3 - __uint_as_float(ahi[3]));

            #pragma unroll
            for (int n = 0; n < 8; ++n) {
                mma_tf32(acc[m][n], ahi, bh[n]);
                mma_tf32(acc[m][n], ahi, bl[n]);
                mma_tf32(acc[m][n], alo, bh[n]);
            }
        }
    }

    // epilogue: tanh + W2 dot, butterfly over the 4 lanes holding each row
    #pragma unroll
    for (int m = 0; m < 2; ++m) {
        #pragma unroll
        for (int half = 0; half < 2; ++half) {
            float s = 0.0f;
            #pragma unroll
            for (int n = 0; n < 8; ++n) {
                #pragma unroll
                for (int c = 0; c < 2; ++c) {
                    int col = n * 8 + 2 * tq + c;
                    float h = acc[m][n][half * 2 + c] + b1s[col];
                    s = fmaf(tanh_fast(h), w2s[col], s);
                }
            }
            s += __shfl_xor_sync(0xffffffffu, s, 1);
            s += __shfl_xor_sync(0xffffffffu, s, 2);
            if (tq == 0) {
                int node = n0 + base + m * 16 + half * 8 + g;
                if (node < NN) {
                    g_e[t][node] = __expf(s);
                    atomicAdd(&g_count[t][batch[node]], 1);
                }
            }
        }
    }
}

// ---------------- K2: exclusive prefix scan over segments ----------------
__global__ void scan_kernel() {
    __shared__ int ss[BB];
    int tid = threadIdx.x;
    for (int t = 0; t < 2; ++t) {
        int v = g_count[t][tid];
        ss[tid] = v;
        __syncthreads();
        for (int d = 1; d < BB; d <<= 1) {
            int add = (tid >= d) ? ss[tid - d] : 0;
            __syncthreads();
            ss[tid] += add;
            __syncthreads();
        }
        int incl = ss[tid];
        g_offset[t][tid] = incl - v;
        g_cursor[t][tid] = incl - v;
        if (tid == BB - 1) g_offset[t][BB] = incl;
        __syncthreads();
    }
}

// ---------------- K3: scatter nodes into segment-sorted order (x4 ILP) ----------------
__global__ void scatter_kernel(const int* __restrict__ bA, const int* __restrict__ bB) {
    int t = blockIdx.y;
    int i0 = (blockIdx.x * blockDim.x + threadIdx.x) * 4;
    const int* batch = t ? bB : bA;
    int  b[4]; float e[4]; int p[4];
    #pragma unroll
    for (int u = 0; u < 4; ++u) {
        int i = i0 + u;
        if (i < NN) { b[u] = batch[i]; e[u] = g_e[t][i]; }
    }
    #pragma unroll
    for (int u = 0; u < 4; ++u) {
        int i = i0 + u;
        if (i < NN) p[u] = atomicAdd(&g_cursor[t][b[u]], 1);
    }
    #pragma unroll
    for (int u = 0; u < 4; ++u) {
        int i = i0 + u;
        if (i < NN) { g_idx[t][p[u]] = i; g_esort[t][p[u]] = e[u]; }
    }
}

// ---------------- K4: per-segment weighted pooling ----------------
__global__ __launch_bounds__(256) void pool_kernel(
    const float* __restrict__ x1, const float* __restrict__ x2,
    float* __restrict__ out)
{
    const int t = blockIdx.y;
    const int b = blockIdx.x;
    const float* x = t ? x2 : x1;
    const int start = g_offset[t][b];
    const int end   = g_offset[t][b + 1];
    const int f    = threadIdx.x & 127;
    const int slot = threadIdx.x >> 7;

    float acc = 0.0f, es = 0.0f;
    #pragma unroll 4
    for (int p = start + slot; p < end; p += 2) {
        int   n = g_idx[t][p];
        float e = g_esort[t][p];
        acc = fmaf(e, x[n * FF + f], acc);
        es += e;
    }

    __shared__ float sa[128];
    __shared__ float se[2];
    if (slot == 1) { sa[f] = acc; if (f == 0) se[1] = es; }
    else if (f == 0) se[0] = es;
    __syncthreads();

    if (slot == 0 && end > start) {
        float tot = acc + sa[f];
        float s   = se[0] + se[1];
        atomicAdd(&out[b * FF + f], 0.5f * tot / s);
    }
}

// ---------------- launch ----------------
extern "C" void kernel_launch(void* const* d_in, const int* in_sizes, int n_in,
                              void* d_out, int out_size) {
    const float *x1 = 0, *x2 = 0, *W1 = 0, *b1v = 0, *W2 = 0;
    const int *bt1 = 0, *bt2 = 0;
    for (int k = 0; k < n_in; ++k) {
        long s = in_sizes[k];
        if (s == (long)NN * FF) { if (!x1) x1 = (const float*)d_in[k]; else if (!x2) x2 = (const float*)d_in[k]; }
        else if (s == NN)       { if (!bt1) bt1 = (const int*)d_in[k]; else if (!bt2) bt2 = (const int*)d_in[k]; }
        else if (s == FF * HH)  { W1 = (const float*)d_in[k]; }
        else if (s == HH)       { if (!b1v) b1v = (const float*)d_in[k]; else if (!W2) W2 = (const float*)d_in[k]; }
    }
    float* out = (float*)d_out;

    init_kernel<<<(BB * FF + 255) / 256, 256>>>(out);

    const int smem_bytes = SMEM_F * (int)sizeof(float);
    cudaFuncSetAttribute(score_mma_kernel, cudaFuncAttributeMaxDynamicSharedMemorySize, smem_bytes);
    dim3 g1((NN + TILE - 1) / TILE, 2);
    score_mma_kernel<<<g1, 128, smem_bytes>>>(x1, x2, bt1, bt2, W1, b1v, W2);

    scan_kernel<<<1, BB>>>();

    dim3 g3((NN / 4 + 255) / 256, 2);
    scatter_kernel<<<g3, 256>>>(bt1, bt2);

    dim3 g4(BB, 2);
    pool_kernel<<<g4, 256>>>(x1, x2, out);
}